// round 11
// baseline (speedup 1.0000x reference)
#include <cuda_runtime.h>
#include <cuda_bf16.h>

// Fused 13-tap depthwise conv (FD-5 composed with Gauss-9), packed f32x2.
//   z[t] = sum_{k=0..12} w[k] * x[t+k],  w symmetric (w[k]==w[12-k]).
// x [8,4,1048576] fp32 -> out [8,4,1048564] fp32 (32 independent rows).
//
// R11: the kernel is ~half fma-pipe-bound (13.6M warp-FFMA at rt=2 ~ 24us,
// memory ~22-26us). Use PTX f32x2 packed ops (fma.rn.f32x2/add.rn.f32x2 —
// not emittable from C++) to process two adjacent outputs per instruction:
// 8 output pairs/thread, 13 packed ops per pair (1 mul2 + 6 add2 + 6 fma2)
// = 104 fma-pipe instr for 16 outputs (was 208). Fat threads: 16 contiguous
// floats owned per thread (4 batched LDG.128), 12-float halo from lane+1
// via shuffle, lane 31 patched by 3 predicated loads.

#define T_IN 1048576
#define G_IN 262144              // float4 groups per input row
#define G_OUT 262141             // float4 groups per output row (1048564/4)
#define N_ROWS 32
#define BLOCKS_X 256             // 256 blocks * 8 warps * 128 groups = 262144

typedef unsigned long long ull;

__device__ __forceinline__ ull pk2(float lo, float hi) {
    ull r; asm("mov.b64 %0, {%1, %2};" : "=l"(r) : "f"(lo), "f"(hi)); return r;
}
__device__ __forceinline__ void upk2(float& lo, float& hi, ull v) {
    asm("mov.b64 {%0, %1}, %2;" : "=f"(lo), "=f"(hi) : "l"(v));
}
__device__ __forceinline__ ull add2(ull a, ull b) {
    ull r; asm("add.rn.f32x2 %0, %1, %2;" : "=l"(r) : "l"(a), "l"(b)); return r;
}
__device__ __forceinline__ ull mul2(ull a, ull b) {
    ull r; asm("mul.rn.f32x2 %0, %1, %2;" : "=l"(r) : "l"(a), "l"(b)); return r;
}
__device__ __forceinline__ ull fma2(ull a, ull b, ull c) {
    ull r; asm("fma.rn.f32x2 %0, %1, %2, %3;" : "=l"(r) : "l"(a), "l"(b), "l"(c)); return r;
}

__global__ __launch_bounds__(256)
void fused_conv13_f32x2_kernel(const float* __restrict__ x,
                               float4* __restrict__ out,
                               const float* __restrict__ fd,
                               const float* __restrict__ gs) {
    __shared__ float ws[7];

    const int warp = threadIdx.x >> 5;
    const int lane = threadIdx.x & 31;
    const int row  = blockIdx.y;

    // Composite symmetric weights: w[k] = sum_i fd[i]*gauss[k-i], k=0..6.
    if (threadIdx.x < 7) {
        int k = threadIdx.x;
        float s = 0.0f;
        #pragma unroll
        for (int i = 0; i < 5; i++) {
            int j = k - i;
            if (j >= 0 && j < 9) s += fd[i] * gs[j];
        }
        ws[k] = s;
    }

    const float4* __restrict__ in4 = (const float4*)(x + (size_t)row * T_IN);
    float4* __restrict__ out4 = out + (size_t)row * G_OUT;

    const int warpbase = (blockIdx.x * 8 + warp) * 128;  // warp covers 128 groups
    const int gb = warpbase + (lane << 2);               // this thread: groups gb..gb+3

    // ---- Batched primary loads (MLP=4); gb+3 <= 262143, always in-bounds ----
    float4 v0 = in4[gb + 0];
    float4 v1 = in4[gb + 1];
    float4 v2 = in4[gb + 2];
    float4 v3 = in4[gb + 3];

    // Lane-31 halo patch loads (groups warpbase+128..130, clamped for the
    // final warp; clamped garbage only feeds outputs >= G_OUT, never stored).
    float4 p0, p1, p2;
    p0 = p1 = p2 = make_float4(0.f, 0.f, 0.f, 0.f);
    if (lane == 31) {
        p0 = in4[min(warpbase + 128, G_IN - 1)];
        p1 = in4[min(warpbase + 129, G_IN - 1)];
        p2 = in4[min(warpbase + 130, G_IN - 1)];
    }

    __syncthreads();   // weight smem ready; hides under DRAM latency above

    // ---- Window a[0..27]: own 16 floats + 12-float halo from lane+1 ----
    float a[28];
    a[0]=v0.x; a[1]=v0.y; a[2]=v0.z; a[3]=v0.w;
    a[4]=v1.x; a[5]=v1.y; a[6]=v1.z; a[7]=v1.w;
    a[8]=v2.x; a[9]=v2.y; a[10]=v2.z; a[11]=v2.w;
    a[12]=v3.x; a[13]=v3.y; a[14]=v3.z; a[15]=v3.w;

    const bool edge = (lane == 31);
    float h;
    h = __shfl_down_sync(0xffffffffu, a[0], 1);  a[16] = edge ? p0.x : h;
    h = __shfl_down_sync(0xffffffffu, a[1], 1);  a[17] = edge ? p0.y : h;
    h = __shfl_down_sync(0xffffffffu, a[2], 1);  a[18] = edge ? p0.z : h;
    h = __shfl_down_sync(0xffffffffu, a[3], 1);  a[19] = edge ? p0.w : h;
    h = __shfl_down_sync(0xffffffffu, a[4], 1);  a[20] = edge ? p1.x : h;
    h = __shfl_down_sync(0xffffffffu, a[5], 1);  a[21] = edge ? p1.y : h;
    h = __shfl_down_sync(0xffffffffu, a[6], 1);  a[22] = edge ? p1.z : h;
    h = __shfl_down_sync(0xffffffffu, a[7], 1);  a[23] = edge ? p1.w : h;
    h = __shfl_down_sync(0xffffffffu, a[8], 1);  a[24] = edge ? p2.x : h;
    h = __shfl_down_sync(0xffffffffu, a[9], 1);  a[25] = edge ? p2.y : h;
    h = __shfl_down_sync(0xffffffffu, a[10], 1); a[26] = edge ? p2.z : h;
    h = __shfl_down_sync(0xffffffffu, a[11], 1); a[27] = edge ? p2.w : h;

    // Packed weight pairs (w,w)
    ull W[7];
    #pragma unroll
    for (int k = 0; k < 7; k++) { float wv = ws[k]; W[k] = pk2(wv, wv); }

    // Aligned pairs AP[i]=(a[2i],a[2i+1]) and misaligned M[i]=(a[2i+1],a[2i+2])
    ull AP[14], M[13];
    #pragma unroll
    for (int i = 0; i < 14; i++) AP[i] = pk2(a[2*i], a[2*i + 1]);
    #pragma unroll
    for (int i = 0; i < 13; i++) M[i] = pk2(a[2*i + 1], a[2*i + 2]);

    // ---- 8 packed output pairs: 1 mul2 + 6 add2 + 6 fma2 each ----
    float o[16];
    #pragma unroll
    for (int p = 0; p < 8; p++) {
        ull acc = mul2(W[6], AP[p + 3]);                    // center tap
        acc = fma2(W[0], add2(AP[p],     AP[p + 6]), acc);  // k=0 / 12
        acc = fma2(W[2], add2(AP[p + 1], AP[p + 5]), acc);  // k=2 / 10
        acc = fma2(W[4], add2(AP[p + 2], AP[p + 4]), acc);  // k=4 / 8
        acc = fma2(W[1], add2(M[p],      M[p + 5]),  acc);  // k=1 / 11
        acc = fma2(W[3], add2(M[p + 1],  M[p + 4]),  acc);  // k=3 / 9
        acc = fma2(W[5], add2(M[p + 2],  M[p + 3]),  acc);  // k=5 / 7
        upk2(o[2*p], o[2*p + 1], acc);
    }

    float4 s0 = make_float4(o[0],  o[1],  o[2],  o[3]);
    float4 s1 = make_float4(o[4],  o[5],  o[6],  o[7]);
    float4 s2 = make_float4(o[8],  o[9],  o[10], o[11]);
    float4 s3 = make_float4(o[12], o[13], o[14], o[15]);

    if (gb + 3 < G_OUT) {            // all but the final thread of each row
        out4[gb + 0] = s0;
        out4[gb + 1] = s1;
        out4[gb + 2] = s2;
        out4[gb + 3] = s3;
    } else {
        if (gb     < G_OUT) out4[gb    ] = s0;
        if (gb + 1 < G_OUT) out4[gb + 1] = s1;
        if (gb + 2 < G_OUT) out4[gb + 2] = s2;
        if (gb + 3 < G_OUT) out4[gb + 3] = s3;
    }
}

extern "C" void kernel_launch(void* const* d_in, const int* in_sizes, int n_in,
                              void* d_out, int out_size) {
    const float* x  = (const float*)d_in[0];   // [8,4,1048576]
    const float* fd = (const float*)d_in[1];   // [5]
    const float* gs = (const float*)d_in[2];   // [9]
    float4* out = (float4*)d_out;              // [8,4,1048564] as float4 groups

    dim3 grid(BLOCKS_X, N_ROWS);
    fused_conv13_f32x2_kernel<<<grid, 256>>>(x, out, fd, gs);
}